// round 13
// baseline (speedup 1.0000x reference)
#include <cuda_runtime.h>
#include <math.h>

// MT 1D forward + loss, fused. Output: [total, loss_rhoa, loss_phase].
//
// R13: ZERO-MUFU mainloop. The per-step transcendentals E=exp(-(1+i)a) are
// replaced by a 512-entry shared table over a in [0,14.2] (Delta=1/36) plus
// a 2nd-order Taylor correction E(a0+h)=E(a0)*((1-h)+i(h^2-h)), err<=1.3e-6.
// Rationale: all R4-R12 configs shared one invariant -- chip-total MUFU work
// (3 MUFU/layer-step -> ~5.3K cyc/SMSP at rt=8) -- and all were pinned at
// 13.3-15us. Table lookup moves that work to the fma pipe (+5 slots/step)
// and LDS broadcast (adjacent lanes have near-identical a).
//
// Structure as R12: k=4 warp-split chains (1 vector + 3 matrix warps),
// 512 blocks x 128 threads, shared-memory combine, ticket-fused reduction.
// Layer map on (U,V): M_j=[[1,-rE],[r,-E]], r=(g-1)/(g+1); scale-invariant,
// renorm every 8 steps; outputs division-free.

#define MUF 1.25663706143591729e-6f   // 4*pi*1e-7
#define TWO_PI_F 6.2831853071795864f
#define RAD2DEG_F 57.295779513082321f
#define TBL_N 512
#define TBL_SCALE 36.0f               // 1/Delta
#define TBL_DELTA (1.0f / 36.0f)

__device__ float2 g_part[512];
__device__ unsigned int g_ticket;     // zero-init; last block resets each launch

__device__ __forceinline__ float frcp_fast(float x) {
    float r; asm("rcp.approx.ftz.f32 %0,%1;" : "=f"(r) : "f"(x)); return r;
}
__device__ __forceinline__ float frnd_rni(float x) {
    float r; asm("cvt.rni.f32.f32 %0,%1;" : "=f"(r) : "f"(x)); return r;
}

// E = er - i*ei from table + Taylor-2 correction. 0 MUFU.
// sT = s*TBL_SCALE (per-thread const). a = s*coef = (sT*coef)*Delta.
__device__ __forceinline__ void e_tab(const float2* __restrict__ T,
                                      float coef, float sT,
                                      float& er, float& ei)
{
    float t  = sT * coef;              // a / Delta, in [0, ~498]
    t = fminf(t, 511.0f);              // safety clamp
    float kf = frnd_rni(t);
    float ht = t - kf;                 // [-0.5, 0.5]
    float h  = ht * TBL_DELTA;         // a - a0
    int   k  = (int)kf;
    float2 E0 = T[k];                  // (er0, ei0), broadcast-friendly
    float cr = 1.0f - h;               // Re e^{-(1+i)h}
    float cm = fmaf(h, h, -h);         // Im e^{-(1+i)h}
    er = fmaf(E0.y, cm, E0.x * cr);
    ei = fmaf(-E0.x, cm, E0.y * cr);
}

__global__ __launch_bounds__(128, 8)
void mt_fused(const float* __restrict__ res,
              const float* __restrict__ thick,
              const float* __restrict__ freq,
              const float* __restrict__ orhoa,
              const float* __restrict__ ophase,
              float* __restrict__ out,
              int nz, int nf, float inv_nf)
{
    __shared__ float2 lay[512];        // (coef_j, r_j), deepest layer first
    __shared__ float2 etbl[TBL_N];     // E(a_k) = (e^-a cos a, e^-a sin a)
    __shared__ float  pmat[3][32][9];  // matrix-warp products (+pad)
    __shared__ float  sc_x0, sc_lrho0;
    __shared__ float2 red[4];
    __shared__ int    is_last;

    const int nl  = nz - 1;
    const int tid = threadIdx.x;

    for (int i = tid; i < nl; i += blockDim.x) {
        int   j   = nl - 1 - i;                    // deepest first
        float rho = res[j];
        float t   = thick[j];
        float g   = (j >= 1) ? sqrtf(rho / res[j - 1]) : 1.0f;
        lay[i] = make_float2(t * sqrtf(2.0f * MUF / rho),
                             (g - 1.0f) / (g + 1.0f));
    }
    for (int i = tid; i < TBL_N; i += blockDim.x) {
        float a  = (float)i * TBL_DELTA;
        float em = __expf(-a);
        float sa, ca;
        __sincosf(a, &sa, &ca);
        etbl[i] = make_float2(em * ca, em * sa);
    }
    if (tid == 0) {
        sc_x0    = sqrtf(res[nz - 1] / res[nz - 2]);
        sc_lrho0 = log10f(res[0]);
    }
    __syncthreads();

    const int wid  = tid >> 5;         // 0 = vector, 1..3 = matrix
    const int lane = tid & 31;
    const int fq   = blockIdx.x * 32 + lane;

    // instr-balanced split (vector ~21 slots/step, matrix ~29)
    const int lm = (21 * nl) / 92;                 // 58 for nl=255
    const int lv = nl - 3 * lm;                    // 81 for nl=255

    float lr = 0.0f, lp = 0.0f;

    float omega = TWO_PI_F * __ldg(&freq[min(fq, nf - 1)]);
    float s     = sqrtf(omega);
    float sT    = s * TBL_SCALE;

    if (wid == 0) {
        // ---- vector warp: deepest lv layers applied to v0 ----
        float x0 = sc_x0;
        float Ur = x0 + 1.0f, Ui = 0.0f;
        float Vr = x0 - 1.0f, Vi = 0.0f;

        int i = 0;
        for (; i + 8 <= lv; i += 8) {
            #pragma unroll
            for (int u = 0; u < 8; ++u) {
                float2 L = lay[i + u];
                float er, ei;
                e_tab(etbl, L.x, sT, er, ei);
                float wr = er * Vr + ei * Vi;      // w = E*V
                float wi = er * Vi - ei * Vr;
                float r  = L.y;
                float nUr = fmaf(-r, wr, Ur);
                float nUi = fmaf(-r, wi, Ui);
                float nVr = fmaf( r, Ur, -wr);
                float nVi = fmaf( r, Ui, -wi);
                Ur = nUr; Ui = nUi; Vr = nVr; Vi = nVi;
            }
            float m = frcp_fast(fabsf(Ur) + fabsf(Ui));
            Ur *= m; Ui *= m; Vr *= m; Vi *= m;
        }
        for (; i < lv; ++i) {
            float2 L = lay[i];
            float er, ei;
            e_tab(etbl, L.x, sT, er, ei);
            float wr = er * Vr + ei * Vi;
            float wi = er * Vi - ei * Vr;
            float r  = L.y;
            float nUr = fmaf(-r, wr, Ur);
            float nUi = fmaf(-r, wi, Ui);
            float nVr = fmaf( r, Ur, -wr);
            float nVi = fmaf( r, Ui, -wi);
            Ur = nUr; Ui = nUi; Vr = nVr; Vi = nVi;
        }

        __syncthreads();               // wait for matrix warps' pmat writes

        #pragma unroll
        for (int q = 0; q < 3; ++q) {
            const float* P = pmat[q][lane];
            float p00r = P[0], p00i = P[1], p01r = P[2], p01i = P[3];
            float p10r = P[4], p10i = P[5], p11r = P[6], p11i = P[7];
            float nUr = p00r * Ur - p00i * Ui + p01r * Vr - p01i * Vi;
            float nUi = p00r * Ui + p00i * Ur + p01r * Vi + p01i * Vr;
            float nVr = p10r * Ur - p10i * Ui + p11r * Vr - p11i * Vi;
            float nVi = p10r * Ui + p10i * Ur + p11r * Vi + p11i * Vr;
            float m = frcp_fast(fabsf(nUr) + fabsf(nUi));
            Ur = nUr * m; Ui = nUi * m; Vr = nVr * m; Vi = nVi * m;
        }

        if (fq < nf) {
            float Nr = Ur + Vr, Ni = Ui + Vi;
            float Dr = Ur - Vr, Di = Ui - Vi;
            float n2 = fmaxf(Nr * Nr + Ni * Ni, 1e-30f);
            float d2 = fmaxf(Dr * Dr + Di * Di, 1e-30f);
            float A  = Nr * Dr + Ni * Di;
            float B  = Ni * Dr - Nr * Di;
            float e1 = sc_lrho0 + log10f(n2) - log10f(d2) - log10f(__ldg(&orhoa[fq]));
            float ph = atan2f(A + B, A - B) * RAD2DEG_F;
            float e2 = ph - __ldg(&ophase[fq]);
            lr = e1 * e1;
            lp = e2 * e2;
        }
    } else {
        // ---- matrix warp wid: layers [lv+(wid-1)*lm, lv+wid*lm) ----
        const int start = lv + (wid - 1) * lm;
        const int end   = start + lm;

        float p00r = 1.0f, p00i = 0.0f, p01r = 0.0f, p01i = 0.0f;
        float p10r = 0.0f, p10i = 0.0f, p11r = 1.0f, p11i = 0.0f;

        int i = start;
        for (; i + 8 <= end; i += 8) {
            #pragma unroll
            for (int u = 0; u < 8; ++u) {
                float2 L = lay[i + u];
                float er, ei;
                e_tab(etbl, L.x, sT, er, ei);
                float r = L.y;
                float Xr = er * p10r + ei * p10i;  // X = E*p10 (E = er - i*ei)
                float Xi = er * p10i - ei * p10r;
                float Yr = er * p11r + ei * p11i;  // Y = E*p11
                float Yi = er * p11i - ei * p11r;
                float n00r = fmaf(-r, Xr, p00r);
                float n00i = fmaf(-r, Xi, p00i);
                float n01r = fmaf(-r, Yr, p01r);
                float n01i = fmaf(-r, Yi, p01i);
                float n10r = fmaf( r, p00r, -Xr);
                float n10i = fmaf( r, p00i, -Xi);
                float n11r = fmaf( r, p01r, -Yr);
                float n11i = fmaf( r, p01i, -Yi);
                p00r = n00r; p00i = n00i; p01r = n01r; p01i = n01i;
                p10r = n10r; p10i = n10i; p11r = n11r; p11i = n11i;
            }
            float m = frcp_fast(fabsf(p00r) + fabsf(p00i)
                              + fabsf(p10r) + fabsf(p10i));
            p00r *= m; p00i *= m; p01r *= m; p01i *= m;
            p10r *= m; p10i *= m; p11r *= m; p11i *= m;
        }
        for (; i < end; ++i) {
            float2 L = lay[i];
            float er, ei;
            e_tab(etbl, L.x, sT, er, ei);
            float r = L.y;
            float Xr = er * p10r + ei * p10i;
            float Xi = er * p10i - ei * p10r;
            float Yr = er * p11r + ei * p11i;
            float Yi = er * p11i - ei * p11r;
            float n00r = fmaf(-r, Xr, p00r);
            float n00i = fmaf(-r, Xi, p00i);
            float n01r = fmaf(-r, Yr, p01r);
            float n01i = fmaf(-r, Yi, p01i);
            float n10r = fmaf( r, p00r, -Xr);
            float n10i = fmaf( r, p00i, -Xi);
            float n11r = fmaf( r, p01r, -Yr);
            float n11i = fmaf( r, p01i, -Yi);
            p00r = n00r; p00i = n00i; p01r = n01r; p01i = n01i;
            p10r = n10r; p10i = n10i; p11r = n11r; p11i = n11i;
        }

        float* P = pmat[wid - 1][lane];
        P[0] = p00r; P[1] = p00i; P[2] = p01r; P[3] = p01i;
        P[4] = p10r; P[5] = p10i; P[6] = p11r; P[7] = p11i;
        __syncthreads();               // publish to vector warp
    }

    // deterministic block reduction (4 warps; only warp 0 nonzero)
    const unsigned FULL = 0xffffffffu;
    #pragma unroll
    for (int o = 16; o > 0; o >>= 1) {
        lr += __shfl_down_sync(FULL, lr, o);
        lp += __shfl_down_sync(FULL, lp, o);
    }
    if (lane == 0) red[wid] = make_float2(lr, lp);
    __syncthreads();
    if (tid == 0) {
        float slr = red[0].x + red[1].x + red[2].x + red[3].x;
        float slp = red[0].y + red[1].y + red[2].y + red[3].y;
        g_part[blockIdx.x] = make_float2(slr, slp);
        __threadfence();
        unsigned t = atomicAdd(&g_ticket, 1u);
        is_last = (t == gridDim.x - 1) ? 1 : 0;
    }
    __syncthreads();

    if (is_last) {
        __threadfence();
        float flr = 0.0f, flp = 0.0f;
        if (tid < 32) {
            for (int i = tid; i < (int)gridDim.x; i += 32) {
                volatile float* vp = (volatile float*)&g_part[i];
                flr += vp[0];
                flp += vp[1];
            }
            #pragma unroll
            for (int o = 16; o > 0; o >>= 1) {
                flr += __shfl_down_sync(FULL, flr, o);
                flp += __shfl_down_sync(FULL, flp, o);
            }
            if (tid == 0) {
                float mlr = flr * inv_nf;
                float mlp = flp * inv_nf;
                out[0] = mlr + 10.0f * mlp;   // LAMBDA_RHOA=1, LAMBDA_PHASE=10
                out[1] = mlr;
                out[2] = mlp;
                g_ticket = 0;                 // reset for next graph replay
            }
        }
    }
}

extern "C" void kernel_launch(void* const* d_in, const int* in_sizes, int n_in,
                              void* d_out, int out_size)
{
    const float* res = (const float*)d_in[0];
    const float* th  = (const float*)d_in[1];
    const float* fr  = (const float*)d_in[2];
    const float* orh = (const float*)d_in[3];
    const float* oph = (const float*)d_in[4];
    int nz = in_sizes[0];
    int nf = in_sizes[2];

    const int threads = 128;               // 4 warps: 1 vector + 3 matrix
    int blocks = (nf + 31) / 32;           // 512 blocks over 148 SMs
    if (blocks > 512) blocks = 512;

    mt_fused<<<blocks, threads>>>(res, th, fr, orh, oph,
                                  (float*)d_out, nz, nf, 1.0f / (float)nf);
}